// round 12
// baseline (speedup 1.0000x reference)
#include <cuda_runtime.h>

#define N_NODES 50000
#define N_EDGES 1600000
#define HID 64
#define FULL 0xffffffffu
#define BN_EPS 1e-5f
#define INV_N (1.f / (float)N_NODES)

// ---- packed f32x2 helpers ----------------------------------------------------
#define FMA2(d, a, b, c) \
    asm("fma.rn.f32x2 %0, %1, %2, %3;" : "=l"(d) : "l"(a), "l"(b), "l"(c))
#define PACKF2(d, x, y) \
    asm("mov.b64 %0, {%1, %2};" : "=l"(d) : "r"(__float_as_uint(x)), "r"(__float_as_uint(y)))

__device__ __forceinline__ float relu_sum(unsigned long long a) {
    unsigned int lo, hi;
    asm("mov.b64 {%0, %1}, %2;" : "=r"(lo), "=r"(hi) : "l"(a));
    return fmaxf(__uint_as_float(lo) + __uint_as_float(hi), 0.f);
}

// ---------------- scratch (device globals; no allocation allowed) -------------
__device__ int   g_deg[N_NODES];
__device__ int   g_cursor[N_NODES];
__device__ int   g_rowstart[N_NODES + 1];
__device__ int   g_ssrc[N_EDGES];
__device__ float g_z0[N_NODES];
__device__ __align__(16) float g_z[N_NODES * HID];
__device__ __align__(16) float g_y[N_NODES * HID];
__device__ __align__(16) float g_stats[4 * 2 * HID];   // per-layer: [sum(64)|sq(64)]

// ---------------- CSR build ---------------------------------------------------
__global__ void k_zero() {
    int i = blockIdx.x * blockDim.x + threadIdx.x;
    if (i < N_NODES) { g_deg[i] = 0; g_z0[i] = 0.f; }
    if (i < 4 * 2 * HID) g_stats[i] = 0.f;
}

__global__ void k_hist(const int* __restrict__ dst) {
    int e4 = blockIdx.x * blockDim.x + threadIdx.x;
    if (e4 < N_EDGES / 4) {
        int4 d = ((const int4*)dst)[e4];
        atomicAdd(&g_deg[d.x], 1);
        atomicAdd(&g_deg[d.y], 1);
        atomicAdd(&g_deg[d.z], 1);
        atomicAdd(&g_deg[d.w], 1);
    }
}

__global__ void k_scan() {
    __shared__ int part[1024];
    const int CH = (N_NODES + 1023) / 1024;   // 49
    int tid = threadIdx.x;
    int base = tid * CH;
    int s = 0;
    for (int j = 0; j < CH; j++) {
        int idx = base + j;
        if (idx < N_NODES) s += g_deg[idx];
    }
    part[tid] = s;
    __syncthreads();
    for (int off = 1; off < 1024; off <<= 1) {
        int v = (tid >= off) ? part[tid - off] : 0;
        __syncthreads();
        if (tid >= off) part[tid] += v;
        __syncthreads();
    }
    int run = (tid > 0) ? part[tid - 1] : 0;
    for (int j = 0; j < CH; j++) {
        int idx = base + j;
        if (idx < N_NODES) {
            g_rowstart[idx] = run;
            g_cursor[idx]   = run;
            run += g_deg[idx];
        }
    }
    if (tid == 1023) g_rowstart[N_NODES] = part[1023];
}

// permute + fused layer-1 scalar aggregation (x[src] scattered into g_z0[dst])
__global__ void k_permute(const int* __restrict__ src, const int* __restrict__ dst,
                          const float* __restrict__ x) {
    int e4 = blockIdx.x * blockDim.x + threadIdx.x;
    if (e4 < N_EDGES / 4) {
        int4 d = ((const int4*)dst)[e4];
        int4 s = ((const int4*)src)[e4];
        g_ssrc[atomicAdd(&g_cursor[d.x], 1)] = s.x;
        g_ssrc[atomicAdd(&g_cursor[d.y], 1)] = s.y;
        g_ssrc[atomicAdd(&g_cursor[d.z], 1)] = s.z;
        g_ssrc[atomicAdd(&g_cursor[d.w], 1)] = s.w;
        atomicAdd(&g_z0[d.x], __ldg(x + s.x));
        atomicAdd(&g_z0[d.y], __ldg(x + s.y));
        atomicAdd(&g_z0[d.z], __ldg(x + s.z));
        atomicAdd(&g_z0[d.w], __ldg(x + s.w));
    }
}

// ---------------- aggregation: persistent warps, contiguous node runs --------
// BN affine (from prev-layer stats) hoisted out of the node loop; rowstart
// chained. Per node: uniform direct-index gather (no shfl of indices).
// z[i][f] = sc[f]*((1+eps)*y[i][f] + sum_j y[j][f]) + sh[f]*((1+eps)+deg)
__global__ void __launch_bounds__(256) k_agg(
    const float* __restrict__ eps, int layer, int slot,
    const float* __restrict__ gamma, const float* __restrict__ beta)
{
    int lane = threadIdx.x & 31;
    int half = lane >> 4, lq = lane & 15;
    int wid = (blockIdx.x * blockDim.x + threadIdx.x) >> 5;
    int nwarp = (gridDim.x * blockDim.x) >> 5;
    int per = (N_NODES + nwarp - 1) / nwarp;
    int n0 = wid * per;
    if (n0 >= N_NODES) return;
    int n1 = min(n0 + per, N_NODES);

    // hoisted: BN affine for this layer (depends only on lq)
    float ep = 1.f + eps[layer];
    const float* st = g_stats + slot * 128;
    float4 s4 = ((const float4*)st)[lq];
    float4 q4 = ((const float4*)(st + 64))[lq];
    float4 gm = ((const float4*)gamma)[lq];
    float4 bt = ((const float4*)beta)[lq];
    float4 mu, sc, sh;
    mu.x = s4.x * INV_N; mu.y = s4.y * INV_N;
    mu.z = s4.z * INV_N; mu.w = s4.w * INV_N;
    sc.x = gm.x * rsqrtf(fmaf(q4.x, INV_N, -mu.x * mu.x) + BN_EPS);
    sc.y = gm.y * rsqrtf(fmaf(q4.y, INV_N, -mu.y * mu.y) + BN_EPS);
    sc.z = gm.z * rsqrtf(fmaf(q4.z, INV_N, -mu.z * mu.z) + BN_EPS);
    sc.w = gm.w * rsqrtf(fmaf(q4.w, INV_N, -mu.w * mu.w) + BN_EPS);
    sh.x = bt.x - mu.x * sc.x; sh.y = bt.y - mu.y * sc.y;
    sh.z = bt.z - mu.z * sc.z; sh.w = bt.w - mu.w * sc.w;

    const float4* __restrict__ Y4 = (const float4*)g_y;
    const int* __restrict__ sp = g_ssrc;

    int rsPrev = g_rowstart[n0];
    for (int n = n0; n < n1; n++) {
        int rsNext = g_rowstart[n + 1];
        int beg = rsPrev, end = rsNext;
        rsPrev = rsNext;

        float4 a0 = make_float4(0.f, 0.f, 0.f, 0.f);
        float4 a1 = make_float4(0.f, 0.f, 0.f, 0.f);
        float4 a2 = make_float4(0.f, 0.f, 0.f, 0.f);
        float4 a3 = make_float4(0.f, 0.f, 0.f, 0.f);

        int e = beg + half;
        for (; e + 6 < end; e += 8) {
            int s0 = __ldg(sp + e);
            int s1 = __ldg(sp + e + 2);
            int s2 = __ldg(sp + e + 4);
            int s3 = __ldg(sp + e + 6);
            float4 v0 = Y4[s0 * 16 + lq];
            float4 v1 = Y4[s1 * 16 + lq];
            float4 v2 = Y4[s2 * 16 + lq];
            float4 v3 = Y4[s3 * 16 + lq];
            a0.x += v0.x; a0.y += v0.y; a0.z += v0.z; a0.w += v0.w;
            a1.x += v1.x; a1.y += v1.y; a1.z += v1.z; a1.w += v1.w;
            a2.x += v2.x; a2.y += v2.y; a2.z += v2.z; a2.w += v2.w;
            a3.x += v3.x; a3.y += v3.y; a3.z += v3.z; a3.w += v3.w;
        }
        for (; e < end; e += 2) {
            int s0 = __ldg(sp + e);
            float4 v = Y4[s0 * 16 + lq];
            a0.x += v.x; a0.y += v.y; a0.z += v.z; a0.w += v.w;
        }
        a0.x += a1.x + a2.x + a3.x;
        a0.y += a1.y + a2.y + a3.y;
        a0.z += a1.z + a2.z + a3.z;
        a0.w += a1.w + a2.w + a3.w;
        a0.x += __shfl_xor_sync(FULL, a0.x, 16);
        a0.y += __shfl_xor_sync(FULL, a0.y, 16);
        a0.z += __shfl_xor_sync(FULL, a0.z, 16);
        a0.w += __shfl_xor_sync(FULL, a0.w, 16);

        if (half == 0) {
            float dg = ep + (float)(end - beg);
            float4 ys = Y4[n * 16 + lq];
            float4 z;
            z.x = sc.x * fmaf(ep, ys.x, a0.x) + sh.x * dg;
            z.y = sc.y * fmaf(ep, ys.y, a0.y) + sh.y * dg;
            z.z = sc.z * fmaf(ep, ys.z, a0.z) + sh.z * dg;
            z.w = sc.w * fmaf(ep, ys.w, a0.w) + sh.w * dg;
            ((float4*)g_z)[n * 16 + lq] = z;
        }
    }
}

// ---------------- MLP: FFMA2, packed register weights, broadcast LDS.128 -----
// (exact R9/R11 version — best measured)
__global__ void __launch_bounds__(128, 2) k_mlp(
    const float* __restrict__ W1, const float* __restrict__ b1,
    const float* __restrict__ W2, const float* __restrict__ b2, int slot)
{
    __shared__ __align__(16) float zsh[8 * HID];
    __shared__ __align__(16) float tsh[8 * HID];
    __shared__ float red[2][128];

    int tid = threadIdx.x;
    int o = tid & 63, sg = tid >> 6;

    unsigned long long w1p[32], w2p[32];
#pragma unroll
    for (int j = 0; j < 32; j++)
        PACKF2(w1p[j], W1[(2 * j) * HID + o], W1[(2 * j + 1) * HID + o]);
#pragma unroll
    for (int j = 0; j < 32; j++)
        PACKF2(w2p[j], W2[(2 * j) * HID + o], W2[(2 * j + 1) * HID + o]);
    float b1o = b1[o], b2o = b2[o];

    const ulonglong2* zshU = (const ulonglong2*)zsh;
    const ulonglong2* tshU = (const ulonglong2*)tsh;

    float ssum = 0.f, ssq = 0.f;
    const int ngroups = N_NODES / 8;      // 6250
    for (int g = blockIdx.x; g < ngroups; g += gridDim.x) {
        int node0 = g * 8;
        ((float4*)zsh)[tid] = ((const float4*)(g_z + node0 * HID))[tid];
        __syncthreads();

        int l0 = sg * 4;
        unsigned long long ac0, ac1, ac2, ac3;
        PACKF2(ac0, b1o, 0.f); PACKF2(ac1, b1o, 0.f);
        PACKF2(ac2, b1o, 0.f); PACKF2(ac3, b1o, 0.f);
        {
            const ulonglong2* z0 = zshU + (l0 + 0) * 16;
            const ulonglong2* z1 = zshU + (l0 + 1) * 16;
            const ulonglong2* z2 = zshU + (l0 + 2) * 16;
            const ulonglong2* z3 = zshU + (l0 + 3) * 16;
#pragma unroll
            for (int k4 = 0; k4 < 16; k4++) {
                ulonglong2 v0 = z0[k4], v1 = z1[k4], v2 = z2[k4], v3 = z3[k4];
                unsigned long long wA = w1p[2 * k4], wB = w1p[2 * k4 + 1];
                FMA2(ac0, v0.x, wA, ac0); FMA2(ac0, v0.y, wB, ac0);
                FMA2(ac1, v1.x, wA, ac1); FMA2(ac1, v1.y, wB, ac1);
                FMA2(ac2, v2.x, wA, ac2); FMA2(ac2, v2.y, wB, ac2);
                FMA2(ac3, v3.x, wA, ac3); FMA2(ac3, v3.y, wB, ac3);
            }
        }
        tsh[(l0 + 0) * HID + o] = relu_sum(ac0);
        tsh[(l0 + 1) * HID + o] = relu_sum(ac1);
        tsh[(l0 + 2) * HID + o] = relu_sum(ac2);
        tsh[(l0 + 3) * HID + o] = relu_sum(ac3);
        __syncthreads();

        PACKF2(ac0, b2o, 0.f); PACKF2(ac1, b2o, 0.f);
        PACKF2(ac2, b2o, 0.f); PACKF2(ac3, b2o, 0.f);
        {
            const ulonglong2* t0 = tshU + (l0 + 0) * 16;
            const ulonglong2* t1 = tshU + (l0 + 1) * 16;
            const ulonglong2* t2 = tshU + (l0 + 2) * 16;
            const ulonglong2* t3 = tshU + (l0 + 3) * 16;
#pragma unroll
            for (int k4 = 0; k4 < 16; k4++) {
                ulonglong2 v0 = t0[k4], v1 = t1[k4], v2 = t2[k4], v3 = t3[k4];
                unsigned long long wA = w2p[2 * k4], wB = w2p[2 * k4 + 1];
                FMA2(ac0, v0.x, wA, ac0); FMA2(ac0, v0.y, wB, ac0);
                FMA2(ac1, v1.x, wA, ac1); FMA2(ac1, v1.y, wB, ac1);
                FMA2(ac2, v2.x, wA, ac2); FMA2(ac2, v2.y, wB, ac2);
                FMA2(ac3, v3.x, wA, ac3); FMA2(ac3, v3.y, wB, ac3);
            }
        }
        float y0 = relu_sum(ac0), y1 = relu_sum(ac1);
        float y2 = relu_sum(ac2), y3 = relu_sum(ac3);
        g_y[(node0 + l0 + 0) * HID + o] = y0;
        g_y[(node0 + l0 + 1) * HID + o] = y1;
        g_y[(node0 + l0 + 2) * HID + o] = y2;
        g_y[(node0 + l0 + 3) * HID + o] = y3;
        ssum += y0 + y1 + y2 + y3;
        ssq = fmaf(y0, y0, ssq); ssq = fmaf(y1, y1, ssq);
        ssq = fmaf(y2, y2, ssq); ssq = fmaf(y3, y3, ssq);
    }
    red[0][tid] = ssum; red[1][tid] = ssq;
    __syncthreads();
    if (tid < HID) {
        atomicAdd(&g_stats[slot * 128 + tid],      red[0][tid] + red[0][tid + 64]);
        atomicAdd(&g_stats[slot * 128 + 64 + tid], red[1][tid] + red[1][tid + 64]);
    }
}

// ---------------- MLP for layer 1 (scalar -> 64 -> 64), stats slot 0 ---------
// z0 = g_z0 (neighbor sum from k_permute) + (1+eps0)*x
#define MLP_NPB 8
__global__ void __launch_bounds__(128, 3) k_mlp1(
    const float* __restrict__ w1a, const float* __restrict__ b1a,
    const float* __restrict__ W2, const float* __restrict__ b2,
    const float* __restrict__ x, const float* __restrict__ eps)
{
    __shared__ float zs[MLP_NPB];
    __shared__ float tsh[MLP_NPB * HID];
    __shared__ float red[2][128];

    int tid = threadIdx.x;
    int o = tid & 63, sg = tid >> 6;

    float w2r[HID];
#pragma unroll
    for (int k = 0; k < HID; k++) w2r[k] = W2[k * HID + o];
    float w1o = w1a[o], b1o = b1a[o], b2o = b2[o];
    float ep0 = 1.f + eps[0];

    const float4* tsh4 = (const float4*)tsh;

    float ssum = 0.f, ssq = 0.f;
    const int ngroups = N_NODES / MLP_NPB;
    for (int g = blockIdx.x; g < ngroups; g += gridDim.x) {
        int node0 = g * MLP_NPB;
        if (tid < MLP_NPB)
            zs[tid] = fmaf(ep0, x[node0 + tid], g_z0[node0 + tid]);
        __syncthreads();
        tsh[(sg * 4 + 0) * HID + o] = fmaxf(fmaf(zs[sg * 4 + 0], w1o, b1o), 0.f);
        tsh[(sg * 4 + 1) * HID + o] = fmaxf(fmaf(zs[sg * 4 + 1], w1o, b1o), 0.f);
        tsh[(sg * 4 + 2) * HID + o] = fmaxf(fmaf(zs[sg * 4 + 2], w1o, b1o), 0.f);
        tsh[(sg * 4 + 3) * HID + o] = fmaxf(fmaf(zs[sg * 4 + 3], w1o, b1o), 0.f);
        __syncthreads();

        float ac0 = b2o, ac1 = b2o, ac2 = b2o, ac3 = b2o;
        {
            int r0 = (sg * 4 + 0) * 16, r1 = (sg * 4 + 1) * 16;
            int r2 = (sg * 4 + 2) * 16, r3 = (sg * 4 + 3) * 16;
#pragma unroll
            for (int k4 = 0; k4 < 16; k4++) {
                float4 t0 = tsh4[r0 + k4];
                float4 t1 = tsh4[r1 + k4];
                float4 t2 = tsh4[r2 + k4];
                float4 t3 = tsh4[r3 + k4];
                float wa = w2r[4 * k4], wb = w2r[4 * k4 + 1];
                float wc = w2r[4 * k4 + 2], wd = w2r[4 * k4 + 3];
                ac0 = fmaf(t0.x, wa, ac0); ac1 = fmaf(t1.x, wa, ac1);
                ac2 = fmaf(t2.x, wa, ac2); ac3 = fmaf(t3.x, wa, ac3);
                ac0 = fmaf(t0.y, wb, ac0); ac1 = fmaf(t1.y, wb, ac1);
                ac2 = fmaf(t2.y, wb, ac2); ac3 = fmaf(t3.y, wb, ac3);
                ac0 = fmaf(t0.z, wc, ac0); ac1 = fmaf(t1.z, wc, ac1);
                ac2 = fmaf(t2.z, wc, ac2); ac3 = fmaf(t3.z, wc, ac3);
                ac0 = fmaf(t0.w, wd, ac0); ac1 = fmaf(t1.w, wd, ac1);
                ac2 = fmaf(t2.w, wd, ac2); ac3 = fmaf(t3.w, wd, ac3);
            }
        }
        float y0 = fmaxf(ac0, 0.f), y1 = fmaxf(ac1, 0.f);
        float y2 = fmaxf(ac2, 0.f), y3 = fmaxf(ac3, 0.f);
        g_y[(node0 + sg * 4 + 0) * HID + o] = y0;
        g_y[(node0 + sg * 4 + 1) * HID + o] = y1;
        g_y[(node0 + sg * 4 + 2) * HID + o] = y2;
        g_y[(node0 + sg * 4 + 3) * HID + o] = y3;
        ssum += y0 + y1 + y2 + y3;
        ssq  += y0 * y0 + y1 * y1 + y2 * y2 + y3 * y3;
        __syncthreads();
    }
    red[0][tid] = ssum; red[1][tid] = ssq;
    __syncthreads();
    if (tid < HID) {
        atomicAdd(&g_stats[tid],      red[0][tid] + red[0][tid + 64]);
        atomicAdd(&g_stats[64 + tid], red[1][tid] + red[1][tid + 64]);
    }
}

// ---------------- final: out = (BN3(y)) @ fc_w + fc_b, affine inline ---------
__global__ void k_fc(const float* __restrict__ fcw, const float* __restrict__ fcb,
                     const float* __restrict__ gamma, const float* __restrict__ beta,
                     float* __restrict__ out) {
    int gw = (blockIdx.x * blockDim.x + threadIdx.x) >> 5;
    if (gw >= N_NODES) return;
    int lane = threadIdx.x & 31;
    const float* st = g_stats + 3 * 128;
    float2 s2 = ((const float2*)st)[lane];
    float2 q2 = ((const float2*)(st + 64))[lane];
    float2 gm = ((const float2*)gamma)[lane];
    float2 bt = ((const float2*)beta)[lane];
    float mux = s2.x * INV_N, muy = s2.y * INV_N;
    float scx = gm.x * rsqrtf(fmaf(q2.x, INV_N, -mux * mux) + BN_EPS);
    float scy = gm.y * rsqrtf(fmaf(q2.y, INV_N, -muy * muy) + BN_EPS);
    float shx = bt.x - mux * scx;
    float shy = bt.y - muy * scy;
    float2 y  = ((const float2*)g_y)[gw * 32 + lane];
    float2 fw = ((const float2*)fcw)[lane];
    float p = fmaf(fmaf(y.x, scx, shx), fw.x,
                   fmaf(y.y, scy, shy) * fw.y);
#pragma unroll
    for (int off = 16; off; off >>= 1) p += __shfl_down_sync(FULL, p, off);
    if (lane == 0) out[gw] = p + fcb[0];
}

// ---------------- launch ------------------------------------------------------
extern "C" void kernel_launch(void* const* d_in, const int* in_sizes, int n_in,
                              void* d_out, int out_size) {
    const float* x      = (const float*)d_in[0];
    const int*   ei     = (const int*)  d_in[1];
    const int*   src    = ei;
    const int*   dst    = ei + N_EDGES;
    const float* w1a    = (const float*)d_in[2];
    const float* b1a    = (const float*)d_in[3];
    const float* w2a    = (const float*)d_in[4];
    const float* b2a    = (const float*)d_in[5];
    const float* w1s    = (const float*)d_in[6];
    const float* b1s    = (const float*)d_in[7];
    const float* w2s    = (const float*)d_in[8];
    const float* b2s    = (const float*)d_in[9];
    const float* eps    = (const float*)d_in[10];
    const float* gammas = (const float*)d_in[11];
    const float* betas  = (const float*)d_in[12];
    const float* fcw    = (const float*)d_in[13];
    const float* fcb    = (const float*)d_in[14];
    float* out = (float*)d_out;

    const int EB4 = (N_EDGES / 4 + 255) / 256;     // 1563
    const int WB  = (N_NODES * 32 + 255) / 256;    // 6250 (warp per node)
    const int AGG_GRID  = 740;                     // 5920 persistent warps, ~9 nodes each
    const int MLP1_GRID = 444;
    const int MLP_GRID  = 296;                     // 148 SMs x 2 blocks

    // CSR build (every replay; all scratch state re-derived)
    k_zero<<<(N_NODES + 255) / 256, 256>>>();
    k_hist<<<EB4, 256>>>(dst);
    k_scan<<<1, 1024>>>();
    k_permute<<<EB4, 256>>>(src, dst, x);   // also aggregates x[src] -> g_z0[dst]

    // layer 1 (scalar input) -> y, stats slot 0
    k_mlp1<<<MLP1_GRID, 128>>>(w1a, b1a, w2a, b2a, x, eps);

    // layers 2-4: agg (BN of layer l folded, affine hoisted) + FFMA2 MLP
    for (int l = 0; l < 3; l++) {
        k_agg<<<AGG_GRID, 256>>>(eps, l + 1, l, gammas + l * HID, betas + l * HID);
        k_mlp<<<MLP_GRID, 128>>>(w1s + l * HID * HID, b1s + l * HID,
                                 w2s + l * HID * HID, b2s + l * HID, l + 1);
    }

    // final FC with BN(layer 4) folded, affine inline from stats slot 3
    k_fc<<<WB, 256>>>(fcw, fcb, gammas + 3 * HID, betas + 3 * HID, out);
}

// round 13
// speedup vs baseline: 1.1160x; 1.1160x over previous
#include <cuda_runtime.h>

#define N_NODES 50000
#define N_EDGES 1600000
#define HID 64
#define FULL 0xffffffffu
#define BN_EPS 1e-5f
#define INV_N (1.f / (float)N_NODES)

// ---- packed f32x2 helpers ----------------------------------------------------
#define FMA2(d, a, b, c) \
    asm("fma.rn.f32x2 %0, %1, %2, %3;" : "=l"(d) : "l"(a), "l"(b), "l"(c))
#define PACKF2(d, x, y) \
    asm("mov.b64 %0, {%1, %2};" : "=l"(d) : "r"(__float_as_uint(x)), "r"(__float_as_uint(y)))

__device__ __forceinline__ float relu_sum(unsigned long long a) {
    unsigned int lo, hi;
    asm("mov.b64 {%0, %1}, %2;" : "=r"(lo), "=r"(hi) : "l"(a));
    return fmaxf(__uint_as_float(lo) + __uint_as_float(hi), 0.f);
}

// ---------------- scratch (device globals; no allocation allowed) -------------
__device__ int   g_deg[N_NODES + 64];     // padded so int4 scan reads stay in bounds
__device__ int   g_cursor[N_NODES];
__device__ int   g_rowstart[N_NODES + 1];
__device__ int   g_ssrc[N_EDGES];
__device__ float g_z0[N_NODES];
__device__ __align__(16) float g_z[N_NODES * HID];
__device__ __align__(16) float g_y[N_NODES * HID];
__device__ __align__(16) float g_stats[4 * 2 * HID];   // per-layer: [sum(64)|sq(64)]

// ---------------- CSR build ---------------------------------------------------
__global__ void k_zero() {
    int i = blockIdx.x * blockDim.x + threadIdx.x;
    if (i < N_NODES + 64) g_deg[i] = 0;
    if (i < 4 * 2 * HID) g_stats[i] = 0.f;
}

__global__ void k_hist(const int* __restrict__ dst) {
    int e4 = blockIdx.x * blockDim.x + threadIdx.x;
    if (e4 < N_EDGES / 4) {
        int4 d = ((const int4*)dst)[e4];
        atomicAdd(&g_deg[d.x], 1);
        atomicAdd(&g_deg[d.y], 1);
        atomicAdd(&g_deg[d.z], 1);
        atomicAdd(&g_deg[d.w], 1);
    }
}

__global__ void k_scan() {
    __shared__ int part[1024];
    const int CH = 52;                    // 16B-aligned per-thread base; 1024*52 > 50000
    int tid = threadIdx.x;
    int base = tid * CH;
    int s = 0;
    const int4* d4 = (const int4*)(g_deg + base);   // padded array: reads safe
#pragma unroll
    for (int j = 0; j < CH / 4; j++) {
        int4 v = d4[j];
        int idx = base + 4 * j;
        if (idx + 3 < N_NODES) s += v.x + v.y + v.z + v.w;
        else {
            if (idx < N_NODES)     s += v.x;
            if (idx + 1 < N_NODES) s += v.y;
            if (idx + 2 < N_NODES) s += v.z;
        }
    }
    part[tid] = s;
    __syncthreads();
    for (int off = 1; off < 1024; off <<= 1) {
        int v = (tid >= off) ? part[tid - off] : 0;
        __syncthreads();
        if (tid >= off) part[tid] += v;
        __syncthreads();
    }
    int run = (tid > 0) ? part[tid - 1] : 0;
    for (int j = 0; j < CH; j++) {
        int idx = base + j;
        if (idx < N_NODES) {
            g_rowstart[idx] = run;
            g_cursor[idx]   = run;
            run += g_deg[idx];
        }
    }
    if (tid == 1023) g_rowstart[N_NODES] = part[1023];
}

__global__ void k_permute(const int* __restrict__ src, const int* __restrict__ dst) {
    int e4 = blockIdx.x * blockDim.x + threadIdx.x;
    if (e4 < N_EDGES / 4) {
        int4 d = ((const int4*)dst)[e4];
        int4 s = ((const int4*)src)[e4];
        g_ssrc[atomicAdd(&g_cursor[d.x], 1)] = s.x;
        g_ssrc[atomicAdd(&g_cursor[d.y], 1)] = s.y;
        g_ssrc[atomicAdd(&g_cursor[d.z], 1)] = s.z;
        g_ssrc[atomicAdd(&g_cursor[d.w], 1)] = s.w;
    }
}

// ---------------- layer 1 aggregation (scalar features) ----------------------
__global__ void k_agg1(const float* __restrict__ x, const float* __restrict__ eps) {
    int gw = (blockIdx.x * blockDim.x + threadIdx.x) >> 5;
    if (gw >= N_NODES) return;
    int lane = threadIdx.x & 31;
    int beg = g_rowstart[gw], end = g_rowstart[gw + 1];
    float s = 0.f;
    for (int e = beg + lane; e < end; e += 32) s += x[g_ssrc[e]];
#pragma unroll
    for (int off = 16; off; off >>= 1) s += __shfl_down_sync(FULL, s, off);
    if (lane == 0) g_z0[gw] = fmaf(1.f + eps[0], x[gw], s);
}

// ---------------- aggregation: uniform direct-index loop, BN folded ----------
// Warp per node (R11 distribution — HW backfill balances). 16-lane group covers
// the row as float4; half-group h walks edges beg+h, beg+h+2, ...
// Front loop: 8 accumulators (16 edges in flight/warp), then 4, then step-2.
__global__ void k_agg(const float* __restrict__ eps, int layer, int slot,
                      const float* __restrict__ gamma,
                      const float* __restrict__ beta)
{
    int gw = (blockIdx.x * blockDim.x + threadIdx.x) >> 5;
    if (gw >= N_NODES) return;
    int lane = threadIdx.x & 31;
    int half = lane >> 4, lq = lane & 15;
    int beg = g_rowstart[gw], end = g_rowstart[gw + 1];
    const float4* __restrict__ Y4 = (const float4*)g_y;
    const int* __restrict__ sp = g_ssrc;

    float4 a0 = make_float4(0.f, 0.f, 0.f, 0.f);
    float4 a1 = make_float4(0.f, 0.f, 0.f, 0.f);
    float4 a2 = make_float4(0.f, 0.f, 0.f, 0.f);
    float4 a3 = make_float4(0.f, 0.f, 0.f, 0.f);
    float4 a4 = make_float4(0.f, 0.f, 0.f, 0.f);
    float4 a5 = make_float4(0.f, 0.f, 0.f, 0.f);
    float4 a6 = make_float4(0.f, 0.f, 0.f, 0.f);
    float4 a7 = make_float4(0.f, 0.f, 0.f, 0.f);

    int e = beg + half;
    // front loop: 8 edges per half-group per iteration (16 in flight per warp)
    for (; e + 14 < end; e += 16) {
        int s0 = __ldg(sp + e);
        int s1 = __ldg(sp + e + 2);
        int s2 = __ldg(sp + e + 4);
        int s3 = __ldg(sp + e + 6);
        int s4 = __ldg(sp + e + 8);
        int s5 = __ldg(sp + e + 10);
        int s6 = __ldg(sp + e + 12);
        int s7 = __ldg(sp + e + 14);
        float4 v0 = Y4[s0 * 16 + lq];
        float4 v1 = Y4[s1 * 16 + lq];
        float4 v2 = Y4[s2 * 16 + lq];
        float4 v3 = Y4[s3 * 16 + lq];
        float4 v4 = Y4[s4 * 16 + lq];
        float4 v5 = Y4[s5 * 16 + lq];
        float4 v6 = Y4[s6 * 16 + lq];
        float4 v7 = Y4[s7 * 16 + lq];
        a0.x += v0.x; a0.y += v0.y; a0.z += v0.z; a0.w += v0.w;
        a1.x += v1.x; a1.y += v1.y; a1.z += v1.z; a1.w += v1.w;
        a2.x += v2.x; a2.y += v2.y; a2.z += v2.z; a2.w += v2.w;
        a3.x += v3.x; a3.y += v3.y; a3.z += v3.z; a3.w += v3.w;
        a4.x += v4.x; a4.y += v4.y; a4.z += v4.z; a4.w += v4.w;
        a5.x += v5.x; a5.y += v5.y; a5.z += v5.z; a5.w += v5.w;
        a6.x += v6.x; a6.y += v6.y; a6.z += v6.z; a6.w += v6.w;
        a7.x += v7.x; a7.y += v7.y; a7.z += v7.z; a7.w += v7.w;
    }
    // middle loop: 4 edges per half-group
    for (; e + 6 < end; e += 8) {
        int s0 = __ldg(sp + e);
        int s1 = __ldg(sp + e + 2);
        int s2 = __ldg(sp + e + 4);
        int s3 = __ldg(sp + e + 6);
        float4 v0 = Y4[s0 * 16 + lq];
        float4 v1 = Y4[s1 * 16 + lq];
        float4 v2 = Y4[s2 * 16 + lq];
        float4 v3 = Y4[s3 * 16 + lq];
        a0.x += v0.x; a0.y += v0.y; a0.z += v0.z; a0.w += v0.w;
        a1.x += v1.x; a1.y += v1.y; a1.z += v1.z; a1.w += v1.w;
        a2.x += v2.x; a2.y += v2.y; a2.z += v2.z; a2.w += v2.w;
        a3.x += v3.x; a3.y += v3.y; a3.z += v3.z; a3.w += v3.w;
    }
    // remainder: at most 4 iterations
    for (; e < end; e += 2) {
        int s0 = __ldg(sp + e);
        float4 v = Y4[s0 * 16 + lq];
        a0.x += v.x; a0.y += v.y; a0.z += v.z; a0.w += v.w;
    }
    a0.x += a1.x + a2.x + a3.x + a4.x + a5.x + a6.x + a7.x;
    a0.y += a1.y + a2.y + a3.y + a4.y + a5.y + a6.y + a7.y;
    a0.z += a1.z + a2.z + a3.z + a4.z + a5.z + a6.z + a7.z;
    a0.w += a1.w + a2.w + a3.w + a4.w + a5.w + a6.w + a7.w;
    // combine the two half-groups (complementary edges, same features)
    a0.x += __shfl_xor_sync(FULL, a0.x, 16);
    a0.y += __shfl_xor_sync(FULL, a0.y, 16);
    a0.z += __shfl_xor_sync(FULL, a0.z, 16);
    a0.w += __shfl_xor_sync(FULL, a0.w, 16);

    if (half == 0) {
        float ep = 1.f + eps[layer];
        float dg = ep + (float)(end - beg);
        const float* st = g_stats + slot * 128;
        float4 s4v = ((const float4*)st)[lq];
        float4 q4 = ((const float4*)(st + 64))[lq];
        float4 gm = ((const float4*)gamma)[lq];
        float4 bt = ((const float4*)beta)[lq];
        float4 mu, sc, sh;
        mu.x = s4v.x * INV_N; mu.y = s4v.y * INV_N;
        mu.z = s4v.z * INV_N; mu.w = s4v.w * INV_N;
        sc.x = gm.x * rsqrtf(fmaf(q4.x, INV_N, -mu.x * mu.x) + BN_EPS);
        sc.y = gm.y * rsqrtf(fmaf(q4.y, INV_N, -mu.y * mu.y) + BN_EPS);
        sc.z = gm.z * rsqrtf(fmaf(q4.z, INV_N, -mu.z * mu.z) + BN_EPS);
        sc.w = gm.w * rsqrtf(fmaf(q4.w, INV_N, -mu.w * mu.w) + BN_EPS);
        sh.x = bt.x - mu.x * sc.x; sh.y = bt.y - mu.y * sc.y;
        sh.z = bt.z - mu.z * sc.z; sh.w = bt.w - mu.w * sc.w;
        float4 ys = Y4[gw * 16 + lq];
        float4 z;
        z.x = sc.x * fmaf(ep, ys.x, a0.x) + sh.x * dg;
        z.y = sc.y * fmaf(ep, ys.y, a0.y) + sh.y * dg;
        z.z = sc.z * fmaf(ep, ys.z, a0.z) + sh.z * dg;
        z.w = sc.w * fmaf(ep, ys.w, a0.w) + sh.w * dg;
        ((float4*)g_z)[gw * 16 + lq] = z;
    }
}

// ---------------- MLP: FFMA2, packed register weights, broadcast LDS.128 -----
// (exact R9/R11 version — best measured)
__global__ void __launch_bounds__(128, 2) k_mlp(
    const float* __restrict__ W1, const float* __restrict__ b1,
    const float* __restrict__ W2, const float* __restrict__ b2, int slot)
{
    __shared__ __align__(16) float zsh[8 * HID];
    __shared__ __align__(16) float tsh[8 * HID];
    __shared__ float red[2][128];

    int tid = threadIdx.x;
    int o = tid & 63, sg = tid >> 6;

    unsigned long long w1p[32], w2p[32];
#pragma unroll
    for (int j = 0; j < 32; j++)
        PACKF2(w1p[j], W1[(2 * j) * HID + o], W1[(2 * j + 1) * HID + o]);
#pragma unroll
    for (int j = 0; j < 32; j++)
        PACKF2(w2p[j], W2[(2 * j) * HID + o], W2[(2 * j + 1) * HID + o]);
    float b1o = b1[o], b2o = b2[o];

    const ulonglong2* zshU = (const ulonglong2*)zsh;
    const ulonglong2* tshU = (const ulonglong2*)tsh;

    float ssum = 0.f, ssq = 0.f;
    const int ngroups = N_NODES / 8;      // 6250
    for (int g = blockIdx.x; g < ngroups; g += gridDim.x) {
        int node0 = g * 8;
        ((float4*)zsh)[tid] = ((const float4*)(g_z + node0 * HID))[tid];
        __syncthreads();

        int l0 = sg * 4;
        unsigned long long ac0, ac1, ac2, ac3;
        PACKF2(ac0, b1o, 0.f); PACKF2(ac1, b1o, 0.f);
        PACKF2(ac2, b1o, 0.f); PACKF2(ac3, b1o, 0.f);
        {
            const ulonglong2* z0 = zshU + (l0 + 0) * 16;
            const ulonglong2* z1 = zshU + (l0 + 1) * 16;
            const ulonglong2* z2 = zshU + (l0 + 2) * 16;
            const ulonglong2* z3 = zshU + (l0 + 3) * 16;
#pragma unroll
            for (int k4 = 0; k4 < 16; k4++) {
                ulonglong2 v0 = z0[k4], v1 = z1[k4], v2 = z2[k4], v3 = z3[k4];
                unsigned long long wA = w1p[2 * k4], wB = w1p[2 * k4 + 1];
                FMA2(ac0, v0.x, wA, ac0); FMA2(ac0, v0.y, wB, ac0);
                FMA2(ac1, v1.x, wA, ac1); FMA2(ac1, v1.y, wB, ac1);
                FMA2(ac2, v2.x, wA, ac2); FMA2(ac2, v2.y, wB, ac2);
                FMA2(ac3, v3.x, wA, ac3); FMA2(ac3, v3.y, wB, ac3);
            }
        }
        tsh[(l0 + 0) * HID + o] = relu_sum(ac0);
        tsh[(l0 + 1) * HID + o] = relu_sum(ac1);
        tsh[(l0 + 2) * HID + o] = relu_sum(ac2);
        tsh[(l0 + 3) * HID + o] = relu_sum(ac3);
        __syncthreads();

        PACKF2(ac0, b2o, 0.f); PACKF2(ac1, b2o, 0.f);
        PACKF2(ac2, b2o, 0.f); PACKF2(ac3, b2o, 0.f);
        {
            const ulonglong2* t0 = tshU + (l0 + 0) * 16;
            const ulonglong2* t1 = tshU + (l0 + 1) * 16;
            const ulonglong2* t2 = tshU + (l0 + 2) * 16;
            const ulonglong2* t3 = tshU + (l0 + 3) * 16;
#pragma unroll
            for (int k4 = 0; k4 < 16; k4++) {
                ulonglong2 v0 = t0[k4], v1 = t1[k4], v2 = t2[k4], v3 = t3[k4];
                unsigned long long wA = w2p[2 * k4], wB = w2p[2 * k4 + 1];
                FMA2(ac0, v0.x, wA, ac0); FMA2(ac0, v0.y, wB, ac0);
                FMA2(ac1, v1.x, wA, ac1); FMA2(ac1, v1.y, wB, ac1);
                FMA2(ac2, v2.x, wA, ac2); FMA2(ac2, v2.y, wB, ac2);
                FMA2(ac3, v3.x, wA, ac3); FMA2(ac3, v3.y, wB, ac3);
            }
        }
        float y0 = relu_sum(ac0), y1 = relu_sum(ac1);
        float y2 = relu_sum(ac2), y3 = relu_sum(ac3);
        g_y[(node0 + l0 + 0) * HID + o] = y0;
        g_y[(node0 + l0 + 1) * HID + o] = y1;
        g_y[(node0 + l0 + 2) * HID + o] = y2;
        g_y[(node0 + l0 + 3) * HID + o] = y3;
        ssum += y0 + y1 + y2 + y3;
        ssq = fmaf(y0, y0, ssq); ssq = fmaf(y1, y1, ssq);
        ssq = fmaf(y2, y2, ssq); ssq = fmaf(y3, y3, ssq);
    }
    red[0][tid] = ssum; red[1][tid] = ssq;
    __syncthreads();
    if (tid < HID) {
        atomicAdd(&g_stats[slot * 128 + tid],      red[0][tid] + red[0][tid + 64]);
        atomicAdd(&g_stats[slot * 128 + 64 + tid], red[1][tid] + red[1][tid + 64]);
    }
}

// ---------------- MLP for layer 1 (scalar -> 64 -> 64), stats slot 0 ---------
#define MLP_NPB 8
__global__ void __launch_bounds__(128, 3) k_mlp1(
    const float* __restrict__ w1a, const float* __restrict__ b1a,
    const float* __restrict__ W2, const float* __restrict__ b2)
{
    __shared__ float zs[MLP_NPB];
    __shared__ float tsh[MLP_NPB * HID];
    __shared__ float red[2][128];

    int tid = threadIdx.x;
    int o = tid & 63, sg = tid >> 6;

    float w2r[HID];
#pragma unroll
    for (int k = 0; k < HID; k++) w2r[k] = W2[k * HID + o];
    float w1o = w1a[o], b1o = b1a[o], b2o = b2[o];

    const float4* tsh4 = (const float4*)tsh;

    float ssum = 0.f, ssq = 0.f;
    const int ngroups = N_NODES / MLP_NPB;
    for (int g = blockIdx.x; g < ngroups; g += gridDim.x) {
        int node0 = g * MLP_NPB;
        if (tid < MLP_NPB) zs[tid] = g_z0[node0 + tid];
        __syncthreads();
        tsh[(sg * 4 + 0) * HID + o] = fmaxf(fmaf(zs[sg * 4 + 0], w1o, b1o), 0.f);
        tsh[(sg * 4 + 1) * HID + o] = fmaxf(fmaf(zs[sg * 4 + 1], w1o, b1o), 0.f);
        tsh[(sg * 4 + 2) * HID + o] = fmaxf(fmaf(zs[sg * 4 + 2], w1o, b1o), 0.f);
        tsh[(sg * 4 + 3) * HID + o] = fmaxf(fmaf(zs[sg * 4 + 3], w1o, b1o), 0.f);
        __syncthreads();

        float ac0 = b2o, ac1 = b2o, ac2 = b2o, ac3 = b2o;
        {
            int r0 = (sg * 4 + 0) * 16, r1 = (sg * 4 + 1) * 16;
            int r2 = (sg * 4 + 2) * 16, r3 = (sg * 4 + 3) * 16;
#pragma unroll
            for (int k4 = 0; k4 < 16; k4++) {
                float4 t0 = tsh4[r0 + k4];
                float4 t1 = tsh4[r1 + k4];
                float4 t2 = tsh4[r2 + k4];
                float4 t3 = tsh4[r3 + k4];
                float wa = w2r[4 * k4], wb = w2r[4 * k4 + 1];
                float wc = w2r[4 * k4 + 2], wd = w2r[4 * k4 + 3];
                ac0 = fmaf(t0.x, wa, ac0); ac1 = fmaf(t1.x, wa, ac1);
                ac2 = fmaf(t2.x, wa, ac2); ac3 = fmaf(t3.x, wa, ac3);
                ac0 = fmaf(t0.y, wb, ac0); ac1 = fmaf(t1.y, wb, ac1);
                ac2 = fmaf(t2.y, wb, ac2); ac3 = fmaf(t3.y, wb, ac3);
                ac0 = fmaf(t0.z, wc, ac0); ac1 = fmaf(t1.z, wc, ac1);
                ac2 = fmaf(t2.z, wc, ac2); ac3 = fmaf(t3.z, wc, ac3);
                ac0 = fmaf(t0.w, wd, ac0); ac1 = fmaf(t1.w, wd, ac1);
                ac2 = fmaf(t2.w, wd, ac2); ac3 = fmaf(t3.w, wd, ac3);
            }
        }
        float y0 = fmaxf(ac0, 0.f), y1 = fmaxf(ac1, 0.f);
        float y2 = fmaxf(ac2, 0.f), y3 = fmaxf(ac3, 0.f);
        g_y[(node0 + sg * 4 + 0) * HID + o] = y0;
        g_y[(node0 + sg * 4 + 1) * HID + o] = y1;
        g_y[(node0 + sg * 4 + 2) * HID + o] = y2;
        g_y[(node0 + sg * 4 + 3) * HID + o] = y3;
        ssum += y0 + y1 + y2 + y3;
        ssq  += y0 * y0 + y1 * y1 + y2 * y2 + y3 * y3;
        __syncthreads();
    }
    red[0][tid] = ssum; red[1][tid] = ssq;
    __syncthreads();
    if (tid < HID) {
        atomicAdd(&g_stats[tid],      red[0][tid] + red[0][tid + 64]);
        atomicAdd(&g_stats[64 + tid], red[1][tid] + red[1][tid + 64]);
    }
}

// ---------------- final: out = (BN3(y)) @ fc_w + fc_b, affine inline ---------
__global__ void k_fc(const float* __restrict__ fcw, const float* __restrict__ fcb,
                     const float* __restrict__ gamma, const float* __restrict__ beta,
                     float* __restrict__ out) {
    int gw = (blockIdx.x * blockDim.x + threadIdx.x) >> 5;
    if (gw >= N_NODES) return;
    int lane = threadIdx.x & 31;
    const float* st = g_stats + 3 * 128;
    float2 s2 = ((const float2*)st)[lane];
    float2 q2 = ((const float2*)(st + 64))[lane];
    float2 gm = ((const float2*)gamma)[lane];
    float2 bt = ((const float2*)beta)[lane];
    float mux = s2.x * INV_N, muy = s2.y * INV_N;
    float scx = gm.x * rsqrtf(fmaf(q2.x, INV_N, -mux * mux) + BN_EPS);
    float scy = gm.y * rsqrtf(fmaf(q2.y, INV_N, -muy * muy) + BN_EPS);
    float shx = bt.x - mux * scx;
    float shy = bt.y - muy * scy;
    float2 y  = ((const float2*)g_y)[gw * 32 + lane];
    float2 fw = ((const float2*)fcw)[lane];
    float p = fmaf(fmaf(y.x, scx, shx), fw.x,
                   fmaf(y.y, scy, shy) * fw.y);
#pragma unroll
    for (int off = 16; off; off >>= 1) p += __shfl_down_sync(FULL, p, off);
    if (lane == 0) out[gw] = p + fcb[0];
}

// ---------------- launch ------------------------------------------------------
extern "C" void kernel_launch(void* const* d_in, const int* in_sizes, int n_in,
                              void* d_out, int out_size) {
    const float* x      = (const float*)d_in[0];
    const int*   ei     = (const int*)  d_in[1];
    const int*   src    = ei;
    const int*   dst    = ei + N_EDGES;
    const float* w1a    = (const float*)d_in[2];
    const float* b1a    = (const float*)d_in[3];
    const float* w2a    = (const float*)d_in[4];
    const float* b2a    = (const float*)d_in[5];
    const float* w1s    = (const float*)d_in[6];
    const float* b1s    = (const float*)d_in[7];
    const float* w2s    = (const float*)d_in[8];
    const float* b2s    = (const float*)d_in[9];
    const float* eps    = (const float*)d_in[10];
    const float* gammas = (const float*)d_in[11];
    const float* betas  = (const float*)d_in[12];
    const float* fcw    = (const float*)d_in[13];
    const float* fcb    = (const float*)d_in[14];
    float* out = (float*)d_out;

    const int EB4 = (N_EDGES / 4 + 255) / 256;     // 1563
    const int WB  = (N_NODES * 32 + 255) / 256;    // 6250 (warp per node)
    const int MLP1_GRID = 444;
    const int MLP_GRID  = 296;                     // 148 SMs x 2 blocks

    // CSR build (every replay; all scratch state re-derived)
    k_zero<<<(N_NODES + 64 + 255) / 256, 256>>>();
    k_hist<<<EB4, 256>>>(dst);
    k_scan<<<1, 1024>>>();
    k_permute<<<EB4, 256>>>(src, dst);

    // layer 1 (scalar input) -> y, stats slot 0
    k_agg1<<<WB, 256>>>(x, eps);
    k_mlp1<<<MLP1_GRID, 128>>>(w1a, b1a, w2a, b2a);

    // layers 2-4: agg (BN of layer l folded, affine inline) + FFMA2 MLP
    for (int l = 0; l < 3; l++) {
        k_agg<<<WB, 256>>>(eps, l + 1, l, gammas + l * HID, betas + l * HID);
        k_mlp<<<MLP_GRID, 128>>>(w1s + l * HID * HID, b1s + l * HID,
                                 w2s + l * HID * HID, b2s + l * HID, l + 1);
    }

    // final FC with BN(layer 4) folded, affine inline from stats slot 3
    k_fc<<<WB, 256>>>(fcw, fcb, gammas + 3 * HID, betas + 3 * HID, out);
}

// round 14
// speedup vs baseline: 1.2488x; 1.1190x over previous
#include <cuda_runtime.h>

#define N_NODES 50000
#define N_EDGES 1600000
#define HID 64
#define FULL 0xffffffffu
#define BN_EPS 1e-5f
#define INV_N (1.f / (float)N_NODES)

// ---- packed f32x2 helpers ----------------------------------------------------
#define FMA2(d, a, b, c) \
    asm("fma.rn.f32x2 %0, %1, %2, %3;" : "=l"(d) : "l"(a), "l"(b), "l"(c))
#define PACKF2(d, x, y) \
    asm("mov.b64 %0, {%1, %2};" : "=l"(d) : "r"(__float_as_uint(x)), "r"(__float_as_uint(y)))

__device__ __forceinline__ float relu_sum(unsigned long long a) {
    unsigned int lo, hi;
    asm("mov.b64 {%0, %1}, %2;" : "=r"(lo), "=r"(hi) : "l"(a));
    return fmaxf(__uint_as_float(lo) + __uint_as_float(hi), 0.f);
}

// ---------------- scratch (device globals; no allocation allowed) -------------
__device__ int   g_deg[N_NODES];
__device__ int   g_rowstart[N_NODES + 1];
__device__ __align__(16) int g_rank[N_EDGES];   // edge's rank within its dst bucket
__device__ int   g_ssrc[N_EDGES];
__device__ float g_z0[N_NODES];
__device__ __align__(16) float g_z[N_NODES * HID];
__device__ __align__(16) float g_y[N_NODES * HID];
__device__ __align__(16) float g_stats[4 * 2 * HID];   // per-layer: [sum(64)|sq(64)]

// ---------------- CSR build ---------------------------------------------------
__global__ void k_zero() {
    int i = blockIdx.x * blockDim.x + threadIdx.x;
    if (i < N_NODES) g_deg[i] = 0;
    if (i < 4 * 2 * HID) g_stats[i] = 0.f;
}

// histogram; the returned old count is exactly this edge's rank in its bucket
__global__ void k_hist(const int* __restrict__ dst) {
    int e4 = blockIdx.x * blockDim.x + threadIdx.x;
    if (e4 < N_EDGES / 4) {
        int4 d = ((const int4*)dst)[e4];
        int4 r;
        r.x = atomicAdd(&g_deg[d.x], 1);
        r.y = atomicAdd(&g_deg[d.y], 1);
        r.z = atomicAdd(&g_deg[d.z], 1);
        r.w = atomicAdd(&g_deg[d.w], 1);
        ((int4*)g_rank)[e4] = r;
    }
}

__global__ void k_scan() {
    __shared__ int part[1024];
    const int CH = (N_NODES + 1023) / 1024;   // 49
    int tid = threadIdx.x;
    int base = tid * CH;
    int s = 0;
    for (int j = 0; j < CH; j++) {
        int idx = base + j;
        if (idx < N_NODES) s += g_deg[idx];
    }
    part[tid] = s;
    __syncthreads();
    for (int off = 1; off < 1024; off <<= 1) {
        int v = (tid >= off) ? part[tid - off] : 0;
        __syncthreads();
        if (tid >= off) part[tid] += v;
        __syncthreads();
    }
    int run = (tid > 0) ? part[tid - 1] : 0;
    for (int j = 0; j < CH; j++) {
        int idx = base + j;
        if (idx < N_NODES) { g_rowstart[idx] = run; run += g_deg[idx]; }
    }
    if (tid == 1023) g_rowstart[N_NODES] = part[1023];
}

// atomic-free permute: position = rowstart[dst] + rank (rank from k_hist)
__global__ void k_permute(const int* __restrict__ src, const int* __restrict__ dst) {
    int e4 = blockIdx.x * blockDim.x + threadIdx.x;
    if (e4 < N_EDGES / 4) {
        int4 d = ((const int4*)dst)[e4];
        int4 s = ((const int4*)src)[e4];
        int4 r = ((const int4*)g_rank)[e4];
        g_ssrc[g_rowstart[d.x] + r.x] = s.x;
        g_ssrc[g_rowstart[d.y] + r.y] = s.y;
        g_ssrc[g_rowstart[d.z] + r.z] = s.z;
        g_ssrc[g_rowstart[d.w] + r.w] = s.w;
    }
}

// ---------------- layer 1 aggregation (scalar features) ----------------------
__global__ void k_agg1(const float* __restrict__ x, const float* __restrict__ eps) {
    int gw = (blockIdx.x * blockDim.x + threadIdx.x) >> 5;
    if (gw >= N_NODES) return;
    int lane = threadIdx.x & 31;
    int beg = g_rowstart[gw], end = g_rowstart[gw + 1];
    float s = 0.f;
    for (int e = beg + lane; e < end; e += 32) s += x[g_ssrc[e]];
#pragma unroll
    for (int off = 16; off; off >>= 1) s += __shfl_down_sync(FULL, s, off);
    if (lane == 0) g_z0[gw] = fmaf(1.f + eps[0], x[gw], s);
}

// ---------------- aggregation: uniform direct-index loop, BN folded ----------
// (exact R11 version — best measured)
__global__ void k_agg(const float* __restrict__ eps, int layer, int slot,
                      const float* __restrict__ gamma,
                      const float* __restrict__ beta)
{
    int gw = (blockIdx.x * blockDim.x + threadIdx.x) >> 5;
    if (gw >= N_NODES) return;
    int lane = threadIdx.x & 31;
    int half = lane >> 4, lq = lane & 15;
    int beg = g_rowstart[gw], end = g_rowstart[gw + 1];
    const float4* __restrict__ Y4 = (const float4*)g_y;
    const int* __restrict__ sp = g_ssrc;

    float4 a0 = make_float4(0.f, 0.f, 0.f, 0.f);
    float4 a1 = make_float4(0.f, 0.f, 0.f, 0.f);
    float4 a2 = make_float4(0.f, 0.f, 0.f, 0.f);
    float4 a3 = make_float4(0.f, 0.f, 0.f, 0.f);

    int e = beg + half;
    for (; e + 6 < end; e += 8) {
        int s0 = __ldg(sp + e);
        int s1 = __ldg(sp + e + 2);
        int s2 = __ldg(sp + e + 4);
        int s3 = __ldg(sp + e + 6);
        float4 v0 = Y4[s0 * 16 + lq];
        float4 v1 = Y4[s1 * 16 + lq];
        float4 v2 = Y4[s2 * 16 + lq];
        float4 v3 = Y4[s3 * 16 + lq];
        a0.x += v0.x; a0.y += v0.y; a0.z += v0.z; a0.w += v0.w;
        a1.x += v1.x; a1.y += v1.y; a1.z += v1.z; a1.w += v1.w;
        a2.x += v2.x; a2.y += v2.y; a2.z += v2.z; a2.w += v2.w;
        a3.x += v3.x; a3.y += v3.y; a3.z += v3.z; a3.w += v3.w;
    }
    for (; e < end; e += 2) {
        int s0 = __ldg(sp + e);
        float4 v = Y4[s0 * 16 + lq];
        a0.x += v.x; a0.y += v.y; a0.z += v.z; a0.w += v.w;
    }
    a0.x += a1.x + a2.x + a3.x;
    a0.y += a1.y + a2.y + a3.y;
    a0.z += a1.z + a2.z + a3.z;
    a0.w += a1.w + a2.w + a3.w;
    a0.x += __shfl_xor_sync(FULL, a0.x, 16);
    a0.y += __shfl_xor_sync(FULL, a0.y, 16);
    a0.z += __shfl_xor_sync(FULL, a0.z, 16);
    a0.w += __shfl_xor_sync(FULL, a0.w, 16);

    if (half == 0) {
        float ep = 1.f + eps[layer];
        float dg = ep + (float)(end - beg);
        const float* st = g_stats + slot * 128;
        float4 s4 = ((const float4*)st)[lq];
        float4 q4 = ((const float4*)(st + 64))[lq];
        float4 gm = ((const float4*)gamma)[lq];
        float4 bt = ((const float4*)beta)[lq];
        float4 mu, sc, sh;
        mu.x = s4.x * INV_N; mu.y = s4.y * INV_N;
        mu.z = s4.z * INV_N; mu.w = s4.w * INV_N;
        sc.x = gm.x * rsqrtf(fmaf(q4.x, INV_N, -mu.x * mu.x) + BN_EPS);
        sc.y = gm.y * rsqrtf(fmaf(q4.y, INV_N, -mu.y * mu.y) + BN_EPS);
        sc.z = gm.z * rsqrtf(fmaf(q4.z, INV_N, -mu.z * mu.z) + BN_EPS);
        sc.w = gm.w * rsqrtf(fmaf(q4.w, INV_N, -mu.w * mu.w) + BN_EPS);
        sh.x = bt.x - mu.x * sc.x; sh.y = bt.y - mu.y * sc.y;
        sh.z = bt.z - mu.z * sc.z; sh.w = bt.w - mu.w * sc.w;
        float4 ys = Y4[gw * 16 + lq];
        float4 z;
        z.x = sc.x * fmaf(ep, ys.x, a0.x) + sh.x * dg;
        z.y = sc.y * fmaf(ep, ys.y, a0.y) + sh.y * dg;
        z.z = sc.z * fmaf(ep, ys.z, a0.z) + sh.z * dg;
        z.w = sc.w * fmaf(ep, ys.w, a0.w) + sh.w * dg;
        ((float4*)g_z)[gw * 16 + lq] = z;
    }
}

// ---------------- MLP: FFMA2, packed register weights, broadcast LDS.128 -----
// (exact R9/R11 version — best measured)
__global__ void __launch_bounds__(128, 2) k_mlp(
    const float* __restrict__ W1, const float* __restrict__ b1,
    const float* __restrict__ W2, const float* __restrict__ b2, int slot)
{
    __shared__ __align__(16) float zsh[8 * HID];
    __shared__ __align__(16) float tsh[8 * HID];
    __shared__ float red[2][128];

    int tid = threadIdx.x;
    int o = tid & 63, sg = tid >> 6;

    unsigned long long w1p[32], w2p[32];
#pragma unroll
    for (int j = 0; j < 32; j++)
        PACKF2(w1p[j], W1[(2 * j) * HID + o], W1[(2 * j + 1) * HID + o]);
#pragma unroll
    for (int j = 0; j < 32; j++)
        PACKF2(w2p[j], W2[(2 * j) * HID + o], W2[(2 * j + 1) * HID + o]);
    float b1o = b1[o], b2o = b2[o];

    const ulonglong2* zshU = (const ulonglong2*)zsh;
    const ulonglong2* tshU = (const ulonglong2*)tsh;

    float ssum = 0.f, ssq = 0.f;
    const int ngroups = N_NODES / 8;      // 6250
    for (int g = blockIdx.x; g < ngroups; g += gridDim.x) {
        int node0 = g * 8;
        ((float4*)zsh)[tid] = ((const float4*)(g_z + node0 * HID))[tid];
        __syncthreads();

        int l0 = sg * 4;
        unsigned long long ac0, ac1, ac2, ac3;
        PACKF2(ac0, b1o, 0.f); PACKF2(ac1, b1o, 0.f);
        PACKF2(ac2, b1o, 0.f); PACKF2(ac3, b1o, 0.f);
        {
            const ulonglong2* z0 = zshU + (l0 + 0) * 16;
            const ulonglong2* z1 = zshU + (l0 + 1) * 16;
            const ulonglong2* z2 = zshU + (l0 + 2) * 16;
            const ulonglong2* z3 = zshU + (l0 + 3) * 16;
#pragma unroll
            for (int k4 = 0; k4 < 16; k4++) {
                ulonglong2 v0 = z0[k4], v1 = z1[k4], v2 = z2[k4], v3 = z3[k4];
                unsigned long long wA = w1p[2 * k4], wB = w1p[2 * k4 + 1];
                FMA2(ac0, v0.x, wA, ac0); FMA2(ac0, v0.y, wB, ac0);
                FMA2(ac1, v1.x, wA, ac1); FMA2(ac1, v1.y, wB, ac1);
                FMA2(ac2, v2.x, wA, ac2); FMA2(ac2, v2.y, wB, ac2);
                FMA2(ac3, v3.x, wA, ac3); FMA2(ac3, v3.y, wB, ac3);
            }
        }
        tsh[(l0 + 0) * HID + o] = relu_sum(ac0);
        tsh[(l0 + 1) * HID + o] = relu_sum(ac1);
        tsh[(l0 + 2) * HID + o] = relu_sum(ac2);
        tsh[(l0 + 3) * HID + o] = relu_sum(ac3);
        __syncthreads();

        PACKF2(ac0, b2o, 0.f); PACKF2(ac1, b2o, 0.f);
        PACKF2(ac2, b2o, 0.f); PACKF2(ac3, b2o, 0.f);
        {
            const ulonglong2* t0 = tshU + (l0 + 0) * 16;
            const ulonglong2* t1 = tshU + (l0 + 1) * 16;
            const ulonglong2* t2 = tshU + (l0 + 2) * 16;
            const ulonglong2* t3 = tshU + (l0 + 3) * 16;
#pragma unroll
            for (int k4 = 0; k4 < 16; k4++) {
                ulonglong2 v0 = t0[k4], v1 = t1[k4], v2 = t2[k4], v3 = t3[k4];
                unsigned long long wA = w2p[2 * k4], wB = w2p[2 * k4 + 1];
                FMA2(ac0, v0.x, wA, ac0); FMA2(ac0, v0.y, wB, ac0);
                FMA2(ac1, v1.x, wA, ac1); FMA2(ac1, v1.y, wB, ac1);
                FMA2(ac2, v2.x, wA, ac2); FMA2(ac2, v2.y, wB, ac2);
                FMA2(ac3, v3.x, wA, ac3); FMA2(ac3, v3.y, wB, ac3);
            }
        }
        float y0 = relu_sum(ac0), y1 = relu_sum(ac1);
        float y2 = relu_sum(ac2), y3 = relu_sum(ac3);
        g_y[(node0 + l0 + 0) * HID + o] = y0;
        g_y[(node0 + l0 + 1) * HID + o] = y1;
        g_y[(node0 + l0 + 2) * HID + o] = y2;
        g_y[(node0 + l0 + 3) * HID + o] = y3;
        ssum += y0 + y1 + y2 + y3;
        ssq = fmaf(y0, y0, ssq); ssq = fmaf(y1, y1, ssq);
        ssq = fmaf(y2, y2, ssq); ssq = fmaf(y3, y3, ssq);
    }
    red[0][tid] = ssum; red[1][tid] = ssq;
    __syncthreads();
    if (tid < HID) {
        atomicAdd(&g_stats[slot * 128 + tid],      red[0][tid] + red[0][tid + 64]);
        atomicAdd(&g_stats[slot * 128 + 64 + tid], red[1][tid] + red[1][tid + 64]);
    }
}

// ---------------- MLP for layer 1 (scalar -> 64 -> 64), stats slot 0 ---------
#define MLP_NPB 8
__global__ void __launch_bounds__(128, 3) k_mlp1(
    const float* __restrict__ w1a, const float* __restrict__ b1a,
    const float* __restrict__ W2, const float* __restrict__ b2)
{
    __shared__ float zs[MLP_NPB];
    __shared__ float tsh[MLP_NPB * HID];
    __shared__ float red[2][128];

    int tid = threadIdx.x;
    int o = tid & 63, sg = tid >> 6;

    float w2r[HID];
#pragma unroll
    for (int k = 0; k < HID; k++) w2r[k] = W2[k * HID + o];
    float w1o = w1a[o], b1o = b1a[o], b2o = b2[o];

    const float4* tsh4 = (const float4*)tsh;

    float ssum = 0.f, ssq = 0.f;
    const int ngroups = N_NODES / MLP_NPB;
    for (int g = blockIdx.x; g < ngroups; g += gridDim.x) {
        int node0 = g * MLP_NPB;
        if (tid < MLP_NPB) zs[tid] = g_z0[node0 + tid];
        __syncthreads();
        tsh[(sg * 4 + 0) * HID + o] = fmaxf(fmaf(zs[sg * 4 + 0], w1o, b1o), 0.f);
        tsh[(sg * 4 + 1) * HID + o] = fmaxf(fmaf(zs[sg * 4 + 1], w1o, b1o), 0.f);
        tsh[(sg * 4 + 2) * HID + o] = fmaxf(fmaf(zs[sg * 4 + 2], w1o, b1o), 0.f);
        tsh[(sg * 4 + 3) * HID + o] = fmaxf(fmaf(zs[sg * 4 + 3], w1o, b1o), 0.f);
        __syncthreads();

        float ac0 = b2o, ac1 = b2o, ac2 = b2o, ac3 = b2o;
        {
            int r0 = (sg * 4 + 0) * 16, r1 = (sg * 4 + 1) * 16;
            int r2 = (sg * 4 + 2) * 16, r3 = (sg * 4 + 3) * 16;
#pragma unroll
            for (int k4 = 0; k4 < 16; k4++) {
                float4 t0 = tsh4[r0 + k4];
                float4 t1 = tsh4[r1 + k4];
                float4 t2 = tsh4[r2 + k4];
                float4 t3 = tsh4[r3 + k4];
                float wa = w2r[4 * k4], wb = w2r[4 * k4 + 1];
                float wc = w2r[4 * k4 + 2], wd = w2r[4 * k4 + 3];
                ac0 = fmaf(t0.x, wa, ac0); ac1 = fmaf(t1.x, wa, ac1);
                ac2 = fmaf(t2.x, wa, ac2); ac3 = fmaf(t3.x, wa, ac3);
                ac0 = fmaf(t0.y, wb, ac0); ac1 = fmaf(t1.y, wb, ac1);
                ac2 = fmaf(t2.y, wb, ac2); ac3 = fmaf(t3.y, wb, ac3);
                ac0 = fmaf(t0.z, wc, ac0); ac1 = fmaf(t1.z, wc, ac1);
                ac2 = fmaf(t2.z, wc, ac2); ac3 = fmaf(t3.z, wc, ac3);
                ac0 = fmaf(t0.w, wd, ac0); ac1 = fmaf(t1.w, wd, ac1);
                ac2 = fmaf(t2.w, wd, ac2); ac3 = fmaf(t3.w, wd, ac3);
            }
        }
        float y0 = fmaxf(ac0, 0.f), y1 = fmaxf(ac1, 0.f);
        float y2 = fmaxf(ac2, 0.f), y3 = fmaxf(ac3, 0.f);
        g_y[(node0 + sg * 4 + 0) * HID + o] = y0;
        g_y[(node0 + sg * 4 + 1) * HID + o] = y1;
        g_y[(node0 + sg * 4 + 2) * HID + o] = y2;
        g_y[(node0 + sg * 4 + 3) * HID + o] = y3;
        ssum += y0 + y1 + y2 + y3;
        ssq  += y0 * y0 + y1 * y1 + y2 * y2 + y3 * y3;
        __syncthreads();
    }
    red[0][tid] = ssum; red[1][tid] = ssq;
    __syncthreads();
    if (tid < HID) {
        atomicAdd(&g_stats[tid],      red[0][tid] + red[0][tid + 64]);
        atomicAdd(&g_stats[64 + tid], red[1][tid] + red[1][tid + 64]);
    }
}

// ---------------- final: out = (BN3(y)) @ fc_w + fc_b, affine inline ---------
__global__ void k_fc(const float* __restrict__ fcw, const float* __restrict__ fcb,
                     const float* __restrict__ gamma, const float* __restrict__ beta,
                     float* __restrict__ out) {
    int gw = (blockIdx.x * blockDim.x + threadIdx.x) >> 5;
    if (gw >= N_NODES) return;
    int lane = threadIdx.x & 31;
    const float* st = g_stats + 3 * 128;
    float2 s2 = ((const float2*)st)[lane];
    float2 q2 = ((const float2*)(st + 64))[lane];
    float2 gm = ((const float2*)gamma)[lane];
    float2 bt = ((const float2*)beta)[lane];
    float mux = s2.x * INV_N, muy = s2.y * INV_N;
    float scx = gm.x * rsqrtf(fmaf(q2.x, INV_N, -mux * mux) + BN_EPS);
    float scy = gm.y * rsqrtf(fmaf(q2.y, INV_N, -muy * muy) + BN_EPS);
    float shx = bt.x - mux * scx;
    float shy = bt.y - muy * scy;
    float2 y  = ((const float2*)g_y)[gw * 32 + lane];
    float2 fw = ((const float2*)fcw)[lane];
    float p = fmaf(fmaf(y.x, scx, shx), fw.x,
                   fmaf(y.y, scy, shy) * fw.y);
#pragma unroll
    for (int off = 16; off; off >>= 1) p += __shfl_down_sync(FULL, p, off);
    if (lane == 0) out[gw] = p + fcb[0];
}

// ---------------- launch ------------------------------------------------------
extern "C" void kernel_launch(void* const* d_in, const int* in_sizes, int n_in,
                              void* d_out, int out_size) {
    const float* x      = (const float*)d_in[0];
    const int*   ei     = (const int*)  d_in[1];
    const int*   src    = ei;
    const int*   dst    = ei + N_EDGES;
    const float* w1a    = (const float*)d_in[2];
    const float* b1a    = (const float*)d_in[3];
    const float* w2a    = (const float*)d_in[4];
    const float* b2a    = (const float*)d_in[5];
    const float* w1s    = (const float*)d_in[6];
    const float* b1s    = (const float*)d_in[7];
    const float* w2s    = (const float*)d_in[8];
    const float* b2s    = (const float*)d_in[9];
    const float* eps    = (const float*)d_in[10];
    const float* gammas = (const float*)d_in[11];
    const float* betas  = (const float*)d_in[12];
    const float* fcw    = (const float*)d_in[13];
    const float* fcb    = (const float*)d_in[14];
    float* out = (float*)d_out;

    const int EB4 = (N_EDGES / 4 + 255) / 256;     // 1563
    const int WB  = (N_NODES * 32 + 255) / 256;    // 6250 (warp per node)
    const int MLP1_GRID = 444;
    const int MLP_GRID  = 296;                     // 148 SMs x 2 blocks

    // CSR build (every replay; all scratch state re-derived)
    k_zero<<<(N_NODES + 255) / 256, 256>>>();
    k_hist<<<EB4, 256>>>(dst);                 // also records per-edge rank
    k_scan<<<1, 1024>>>();
    k_permute<<<EB4, 256>>>(src, dst);         // atomic-free scatter

    // layer 1 (scalar input) -> y, stats slot 0
    k_agg1<<<WB, 256>>>(x, eps);
    k_mlp1<<<MLP1_GRID, 128>>>(w1a, b1a, w2a, b2a);

    // layers 2-4: agg (BN of layer l folded, affine inline) + FFMA2 MLP
    for (int l = 0; l < 3; l++) {
        k_agg<<<WB, 256>>>(eps, l + 1, l, gammas + l * HID, betas + l * HID);
        k_mlp<<<MLP_GRID, 128>>>(w1s + l * HID * HID, b1s + l * HID,
                                 w2s + l * HID * HID, b2s + l * HID, l + 1);
    }

    // final FC with BN(layer 4) folded, affine inline from stats slot 3
    k_fc<<<WB, 256>>>(fcw, fcb, gammas + 3 * HID, betas + 3 * HID, out);
}

// round 15
// speedup vs baseline: 1.3174x; 1.0550x over previous
#include <cuda_runtime.h>

#define N_NODES 50000
#define N_EDGES 1600000
#define HID 64
#define FULL 0xffffffffu
#define BN_EPS 1e-5f
#define INV_N (1.f / (float)N_NODES)

// ---- packed f32x2 helpers ----------------------------------------------------
#define FMA2(d, a, b, c) \
    asm("fma.rn.f32x2 %0, %1, %2, %3;" : "=l"(d) : "l"(a), "l"(b), "l"(c))
#define PACKF2(d, x, y) \
    asm("mov.b64 %0, {%1, %2};" : "=l"(d) : "r"(__float_as_uint(x)), "r"(__float_as_uint(y)))

__device__ __forceinline__ float relu_sum(unsigned long long a) {
    unsigned int lo, hi;
    asm("mov.b64 {%0, %1}, %2;" : "=r"(lo), "=r"(hi) : "l"(a));
    return fmaxf(__uint_as_float(lo) + __uint_as_float(hi), 0.f);
}

// ---------------- scratch (device globals; no allocation allowed) -------------
// Invariant: g_deg == 0 and g_stats == 0 at entry of every kernel_launch.
// (zero at module load; k_permute re-zeros g_deg, k_hist re-zeros g_stats.)
__device__ int   g_deg[N_NODES];
__device__ int   g_rowstart[N_NODES + 1];
__device__ __align__(16) int g_rank[N_EDGES];   // edge's rank within its dst bucket
__device__ int   g_ssrc[N_EDGES];
__device__ float g_z0[N_NODES];
__device__ __align__(16) float g_z[N_NODES * HID];
__device__ __align__(16) float g_y[N_NODES * HID];
__device__ __align__(16) float g_stats[4 * 2 * HID];   // per-layer: [sum(64)|sq(64)]

// ---------------- CSR build ---------------------------------------------------
// histogram; the returned old count is exactly this edge's rank in its bucket.
// Also zeros g_stats for this invocation (runs before any stats producer).
__global__ void k_hist(const int* __restrict__ dst) {
    int t = blockIdx.x * blockDim.x + threadIdx.x;
    if (t < 4 * 2 * HID) g_stats[t] = 0.f;
    if (t < N_EDGES / 4) {
        int4 d = ((const int4*)dst)[t];
        int4 r;
        r.x = atomicAdd(&g_deg[d.x], 1);
        r.y = atomicAdd(&g_deg[d.y], 1);
        r.z = atomicAdd(&g_deg[d.z], 1);
        r.w = atomicAdd(&g_deg[d.w], 1);
        ((int4*)g_rank)[t] = r;
    }
}

__global__ void k_scan() {
    __shared__ int part[1024];
    const int CH = (N_NODES + 1023) / 1024;   // 49
    int tid = threadIdx.x;
    int base = tid * CH;
    int s = 0;
    for (int j = 0; j < CH; j++) {
        int idx = base + j;
        if (idx < N_NODES) s += g_deg[idx];
    }
    part[tid] = s;
    __syncthreads();
    for (int off = 1; off < 1024; off <<= 1) {
        int v = (tid >= off) ? part[tid - off] : 0;
        __syncthreads();
        if (tid >= off) part[tid] += v;
        __syncthreads();
    }
    int run = (tid > 0) ? part[tid - 1] : 0;
    for (int j = 0; j < CH; j++) {
        int idx = base + j;
        if (idx < N_NODES) { g_rowstart[idx] = run; run += g_deg[idx]; }
    }
    if (tid == 1023) g_rowstart[N_NODES] = part[1023];
}

// atomic-free permute: position = rowstart[dst] + rank (rank from k_hist).
// Also zeros g_deg for the NEXT invocation (deg is dead after k_scan).
__global__ void k_permute(const int* __restrict__ src, const int* __restrict__ dst) {
    int t = blockIdx.x * blockDim.x + threadIdx.x;
    if (t < N_NODES) g_deg[t] = 0;
    if (t < N_EDGES / 4) {
        int4 d = ((const int4*)dst)[t];
        int4 s = ((const int4*)src)[t];
        int4 r = ((const int4*)g_rank)[t];
        g_ssrc[g_rowstart[d.x] + r.x] = s.x;
        g_ssrc[g_rowstart[d.y] + r.y] = s.y;
        g_ssrc[g_rowstart[d.z] + r.z] = s.z;
        g_ssrc[g_rowstart[d.w] + r.w] = s.w;
    }
}

// ---------------- layer 1 aggregation (scalar features) ----------------------
__global__ void k_agg1(const float* __restrict__ x, const float* __restrict__ eps) {
    int gw = (blockIdx.x * blockDim.x + threadIdx.x) >> 5;
    if (gw >= N_NODES) return;
    int lane = threadIdx.x & 31;
    int beg = g_rowstart[gw], end = g_rowstart[gw + 1];
    float s = 0.f;
    for (int e = beg + lane; e < end; e += 32) s += x[g_ssrc[e]];
#pragma unroll
    for (int off = 16; off; off >>= 1) s += __shfl_down_sync(FULL, s, off);
    if (lane == 0) g_z0[gw] = fmaf(1.f + eps[0], x[gw], s);
}

// ---------------- aggregation: uniform direct-index loop, BN folded ----------
// (R11 code, 128-thread blocks for finer HW backfill)
__global__ void k_agg(const float* __restrict__ eps, int layer, int slot,
                      const float* __restrict__ gamma,
                      const float* __restrict__ beta)
{
    int gw = (blockIdx.x * blockDim.x + threadIdx.x) >> 5;
    if (gw >= N_NODES) return;
    int lane = threadIdx.x & 31;
    int half = lane >> 4, lq = lane & 15;
    int beg = g_rowstart[gw], end = g_rowstart[gw + 1];
    const float4* __restrict__ Y4 = (const float4*)g_y;
    const int* __restrict__ sp = g_ssrc;

    float4 a0 = make_float4(0.f, 0.f, 0.f, 0.f);
    float4 a1 = make_float4(0.f, 0.f, 0.f, 0.f);
    float4 a2 = make_float4(0.f, 0.f, 0.f, 0.f);
    float4 a3 = make_float4(0.f, 0.f, 0.f, 0.f);

    int e = beg + half;
    for (; e + 6 < end; e += 8) {
        int s0 = __ldg(sp + e);
        int s1 = __ldg(sp + e + 2);
        int s2 = __ldg(sp + e + 4);
        int s3 = __ldg(sp + e + 6);
        float4 v0 = Y4[s0 * 16 + lq];
        float4 v1 = Y4[s1 * 16 + lq];
        float4 v2 = Y4[s2 * 16 + lq];
        float4 v3 = Y4[s3 * 16 + lq];
        a0.x += v0.x; a0.y += v0.y; a0.z += v0.z; a0.w += v0.w;
        a1.x += v1.x; a1.y += v1.y; a1.z += v1.z; a1.w += v1.w;
        a2.x += v2.x; a2.y += v2.y; a2.z += v2.z; a2.w += v2.w;
        a3.x += v3.x; a3.y += v3.y; a3.z += v3.z; a3.w += v3.w;
    }
    for (; e < end; e += 2) {
        int s0 = __ldg(sp + e);
        float4 v = Y4[s0 * 16 + lq];
        a0.x += v.x; a0.y += v.y; a0.z += v.z; a0.w += v.w;
    }
    a0.x += a1.x + a2.x + a3.x;
    a0.y += a1.y + a2.y + a3.y;
    a0.z += a1.z + a2.z + a3.z;
    a0.w += a1.w + a2.w + a3.w;
    a0.x += __shfl_xor_sync(FULL, a0.x, 16);
    a0.y += __shfl_xor_sync(FULL, a0.y, 16);
    a0.z += __shfl_xor_sync(FULL, a0.z, 16);
    a0.w += __shfl_xor_sync(FULL, a0.w, 16);

    if (half == 0) {
        float ep = 1.f + eps[layer];
        float dg = ep + (float)(end - beg);
        const float* st = g_stats + slot * 128;
        float4 s4 = ((const float4*)st)[lq];
        float4 q4 = ((const float4*)(st + 64))[lq];
        float4 gm = ((const float4*)gamma)[lq];
        float4 bt = ((const float4*)beta)[lq];
        float4 mu, sc, sh;
        mu.x = s4.x * INV_N; mu.y = s4.y * INV_N;
        mu.z = s4.z * INV_N; mu.w = s4.w * INV_N;
        sc.x = gm.x * rsqrtf(fmaf(q4.x, INV_N, -mu.x * mu.x) + BN_EPS);
        sc.y = gm.y * rsqrtf(fmaf(q4.y, INV_N, -mu.y * mu.y) + BN_EPS);
        sc.z = gm.z * rsqrtf(fmaf(q4.z, INV_N, -mu.z * mu.z) + BN_EPS);
        sc.w = gm.w * rsqrtf(fmaf(q4.w, INV_N, -mu.w * mu.w) + BN_EPS);
        sh.x = bt.x - mu.x * sc.x; sh.y = bt.y - mu.y * sc.y;
        sh.z = bt.z - mu.z * sc.z; sh.w = bt.w - mu.w * sc.w;
        float4 ys = Y4[gw * 16 + lq];
        float4 z;
        z.x = sc.x * fmaf(ep, ys.x, a0.x) + sh.x * dg;
        z.y = sc.y * fmaf(ep, ys.y, a0.y) + sh.y * dg;
        z.z = sc.z * fmaf(ep, ys.z, a0.z) + sh.z * dg;
        z.w = sc.w * fmaf(ep, ys.w, a0.w) + sh.w * dg;
        ((float4*)g_z)[gw * 16 + lq] = z;
    }
}

// ---------------- MLP: FFMA2, packed register weights, broadcast LDS.128 -----
// (exact R9/R11 version — best measured)
__global__ void __launch_bounds__(128, 2) k_mlp(
    const float* __restrict__ W1, const float* __restrict__ b1,
    const float* __restrict__ W2, const float* __restrict__ b2, int slot)
{
    __shared__ __align__(16) float zsh[8 * HID];
    __shared__ __align__(16) float tsh[8 * HID];
    __shared__ float red[2][128];

    int tid = threadIdx.x;
    int o = tid & 63, sg = tid >> 6;

    unsigned long long w1p[32], w2p[32];
#pragma unroll
    for (int j = 0; j < 32; j++)
        PACKF2(w1p[j], W1[(2 * j) * HID + o], W1[(2 * j + 1) * HID + o]);
#pragma unroll
    for (int j = 0; j < 32; j++)
        PACKF2(w2p[j], W2[(2 * j) * HID + o], W2[(2 * j + 1) * HID + o]);
    float b1o = b1[o], b2o = b2[o];

    const ulonglong2* zshU = (const ulonglong2*)zsh;
    const ulonglong2* tshU = (const ulonglong2*)tsh;

    float ssum = 0.f, ssq = 0.f;
    const int ngroups = N_NODES / 8;      // 6250
    for (int g = blockIdx.x; g < ngroups; g += gridDim.x) {
        int node0 = g * 8;
        ((float4*)zsh)[tid] = ((const float4*)(g_z + node0 * HID))[tid];
        __syncthreads();

        int l0 = sg * 4;
        unsigned long long ac0, ac1, ac2, ac3;
        PACKF2(ac0, b1o, 0.f); PACKF2(ac1, b1o, 0.f);
        PACKF2(ac2, b1o, 0.f); PACKF2(ac3, b1o, 0.f);
        {
            const ulonglong2* z0 = zshU + (l0 + 0) * 16;
            const ulonglong2* z1 = zshU + (l0 + 1) * 16;
            const ulonglong2* z2 = zshU + (l0 + 2) * 16;
            const ulonglong2* z3 = zshU + (l0 + 3) * 16;
#pragma unroll
            for (int k4 = 0; k4 < 16; k4++) {
                ulonglong2 v0 = z0[k4], v1 = z1[k4], v2 = z2[k4], v3 = z3[k4];
                unsigned long long wA = w1p[2 * k4], wB = w1p[2 * k4 + 1];
                FMA2(ac0, v0.x, wA, ac0); FMA2(ac0, v0.y, wB, ac0);
                FMA2(ac1, v1.x, wA, ac1); FMA2(ac1, v1.y, wB, ac1);
                FMA2(ac2, v2.x, wA, ac2); FMA2(ac2, v2.y, wB, ac2);
                FMA2(ac3, v3.x, wA, ac3); FMA2(ac3, v3.y, wB, ac3);
            }
        }
        tsh[(l0 + 0) * HID + o] = relu_sum(ac0);
        tsh[(l0 + 1) * HID + o] = relu_sum(ac1);
        tsh[(l0 + 2) * HID + o] = relu_sum(ac2);
        tsh[(l0 + 3) * HID + o] = relu_sum(ac3);
        __syncthreads();

        PACKF2(ac0, b2o, 0.f); PACKF2(ac1, b2o, 0.f);
        PACKF2(ac2, b2o, 0.f); PACKF2(ac3, b2o, 0.f);
        {
            const ulonglong2* t0 = tshU + (l0 + 0) * 16;
            const ulonglong2* t1 = tshU + (l0 + 1) * 16;
            const ulonglong2* t2 = tshU + (l0 + 2) * 16;
            const ulonglong2* t3 = tshU + (l0 + 3) * 16;
#pragma unroll
            for (int k4 = 0; k4 < 16; k4++) {
                ulonglong2 v0 = t0[k4], v1 = t1[k4], v2 = t2[k4], v3 = t3[k4];
                unsigned long long wA = w2p[2 * k4], wB = w2p[2 * k4 + 1];
                FMA2(ac0, v0.x, wA, ac0); FMA2(ac0, v0.y, wB, ac0);
                FMA2(ac1, v1.x, wA, ac1); FMA2(ac1, v1.y, wB, ac1);
                FMA2(ac2, v2.x, wA, ac2); FMA2(ac2, v2.y, wB, ac2);
                FMA2(ac3, v3.x, wA, ac3); FMA2(ac3, v3.y, wB, ac3);
            }
        }
        float y0 = relu_sum(ac0), y1 = relu_sum(ac1);
        float y2 = relu_sum(ac2), y3 = relu_sum(ac3);
        g_y[(node0 + l0 + 0) * HID + o] = y0;
        g_y[(node0 + l0 + 1) * HID + o] = y1;
        g_y[(node0 + l0 + 2) * HID + o] = y2;
        g_y[(node0 + l0 + 3) * HID + o] = y3;
        ssum += y0 + y1 + y2 + y3;
        ssq = fmaf(y0, y0, ssq); ssq = fmaf(y1, y1, ssq);
        ssq = fmaf(y2, y2, ssq); ssq = fmaf(y3, y3, ssq);
    }
    red[0][tid] = ssum; red[1][tid] = ssq;
    __syncthreads();
    if (tid < HID) {
        atomicAdd(&g_stats[slot * 128 + tid],      red[0][tid] + red[0][tid + 64]);
        atomicAdd(&g_stats[slot * 128 + 64 + tid], red[1][tid] + red[1][tid + 64]);
    }
}

// ---------------- MLP for layer 1 (scalar -> 64 -> 64), stats slot 0 ---------
#define MLP_NPB 8
__global__ void __launch_bounds__(128, 3) k_mlp1(
    const float* __restrict__ w1a, const float* __restrict__ b1a,
    const float* __restrict__ W2, const float* __restrict__ b2)
{
    __shared__ float zs[MLP_NPB];
    __shared__ float tsh[MLP_NPB * HID];
    __shared__ float red[2][128];

    int tid = threadIdx.x;
    int o = tid & 63, sg = tid >> 6;

    float w2r[HID];
#pragma unroll
    for (int k = 0; k < HID; k++) w2r[k] = W2[k * HID + o];
    float w1o = w1a[o], b1o = b1a[o], b2o = b2[o];

    const float4* tsh4 = (const float4*)tsh;

    float ssum = 0.f, ssq = 0.f;
    const int ngroups = N_NODES / MLP_NPB;
    for (int g = blockIdx.x; g < ngroups; g += gridDim.x) {
        int node0 = g * MLP_NPB;
        if (tid < MLP_NPB) zs[tid] = g_z0[node0 + tid];
        __syncthreads();
        tsh[(sg * 4 + 0) * HID + o] = fmaxf(fmaf(zs[sg * 4 + 0], w1o, b1o), 0.f);
        tsh[(sg * 4 + 1) * HID + o] = fmaxf(fmaf(zs[sg * 4 + 1], w1o, b1o), 0.f);
        tsh[(sg * 4 + 2) * HID + o] = fmaxf(fmaf(zs[sg * 4 + 2], w1o, b1o), 0.f);
        tsh[(sg * 4 + 3) * HID + o] = fmaxf(fmaf(zs[sg * 4 + 3], w1o, b1o), 0.f);
        __syncthreads();

        float ac0 = b2o, ac1 = b2o, ac2 = b2o, ac3 = b2o;
        {
            int r0 = (sg * 4 + 0) * 16, r1 = (sg * 4 + 1) * 16;
            int r2 = (sg * 4 + 2) * 16, r3 = (sg * 4 + 3) * 16;
#pragma unroll
            for (int k4 = 0; k4 < 16; k4++) {
                float4 t0 = tsh4[r0 + k4];
                float4 t1 = tsh4[r1 + k4];
                float4 t2 = tsh4[r2 + k4];
                float4 t3 = tsh4[r3 + k4];
                float wa = w2r[4 * k4], wb = w2r[4 * k4 + 1];
                float wc = w2r[4 * k4 + 2], wd = w2r[4 * k4 + 3];
                ac0 = fmaf(t0.x, wa, ac0); ac1 = fmaf(t1.x, wa, ac1);
                ac2 = fmaf(t2.x, wa, ac2); ac3 = fmaf(t3.x, wa, ac3);
                ac0 = fmaf(t0.y, wb, ac0); ac1 = fmaf(t1.y, wb, ac1);
                ac2 = fmaf(t2.y, wb, ac2); ac3 = fmaf(t3.y, wb, ac3);
                ac0 = fmaf(t0.z, wc, ac0); ac1 = fmaf(t1.z, wc, ac1);
                ac2 = fmaf(t2.z, wc, ac2); ac3 = fmaf(t3.z, wc, ac3);
                ac0 = fmaf(t0.w, wd, ac0); ac1 = fmaf(t1.w, wd, ac1);
                ac2 = fmaf(t2.w, wd, ac2); ac3 = fmaf(t3.w, wd, ac3);
            }
        }
        float y0 = fmaxf(ac0, 0.f), y1 = fmaxf(ac1, 0.f);
        float y2 = fmaxf(ac2, 0.f), y3 = fmaxf(ac3, 0.f);
        g_y[(node0 + sg * 4 + 0) * HID + o] = y0;
        g_y[(node0 + sg * 4 + 1) * HID + o] = y1;
        g_y[(node0 + sg * 4 + 2) * HID + o] = y2;
        g_y[(node0 + sg * 4 + 3) * HID + o] = y3;
        ssum += y0 + y1 + y2 + y3;
        ssq  += y0 * y0 + y1 * y1 + y2 * y2 + y3 * y3;
        __syncthreads();
    }
    red[0][tid] = ssum; red[1][tid] = ssq;
    __syncthreads();
    if (tid < HID) {
        atomicAdd(&g_stats[tid],      red[0][tid] + red[0][tid + 64]);
        atomicAdd(&g_stats[64 + tid], red[1][tid] + red[1][tid + 64]);
    }
}

// ---------------- final: out = (BN3(y)) @ fc_w + fc_b, affine inline ---------
__global__ void k_fc(const float* __restrict__ fcw, const float* __restrict__ fcb,
                     const float* __restrict__ gamma, const float* __restrict__ beta,
                     float* __restrict__ out) {
    int gw = (blockIdx.x * blockDim.x + threadIdx.x) >> 5;
    if (gw >= N_NODES) return;
    int lane = threadIdx.x & 31;
    const float* st = g_stats + 3 * 128;
    float2 s2 = ((const float2*)st)[lane];
    float2 q2 = ((const float2*)(st + 64))[lane];
    float2 gm = ((const float2*)gamma)[lane];
    float2 bt = ((const float2*)beta)[lane];
    float mux = s2.x * INV_N, muy = s2.y * INV_N;
    float scx = gm.x * rsqrtf(fmaf(q2.x, INV_N, -mux * mux) + BN_EPS);
    float scy = gm.y * rsqrtf(fmaf(q2.y, INV_N, -muy * muy) + BN_EPS);
    float shx = bt.x - mux * scx;
    float shy = bt.y - muy * scy;
    float2 y  = ((const float2*)g_y)[gw * 32 + lane];
    float2 fw = ((const float2*)fcw)[lane];
    float p = fmaf(fmaf(y.x, scx, shx), fw.x,
                   fmaf(y.y, scy, shy) * fw.y);
#pragma unroll
    for (int off = 16; off; off >>= 1) p += __shfl_down_sync(FULL, p, off);
    if (lane == 0) out[gw] = p + fcb[0];
}

// ---------------- launch ------------------------------------------------------
extern "C" void kernel_launch(void* const* d_in, const int* in_sizes, int n_in,
                              void* d_out, int out_size) {
    const float* x      = (const float*)d_in[0];
    const int*   ei     = (const int*)  d_in[1];
    const int*   src    = ei;
    const int*   dst    = ei + N_EDGES;
    const float* w1a    = (const float*)d_in[2];
    const float* b1a    = (const float*)d_in[3];
    const float* w2a    = (const float*)d_in[4];
    const float* b2a    = (const float*)d_in[5];
    const float* w1s    = (const float*)d_in[6];
    const float* b1s    = (const float*)d_in[7];
    const float* w2s    = (const float*)d_in[8];
    const float* b2s    = (const float*)d_in[9];
    const float* eps    = (const float*)d_in[10];
    const float* gammas = (const float*)d_in[11];
    const float* betas  = (const float*)d_in[12];
    const float* fcw    = (const float*)d_in[13];
    const float* fcb    = (const float*)d_in[14];
    float* out = (float*)d_out;

    const int EB4 = (N_EDGES / 4 + 255) / 256;       // 1563
    const int WB  = (N_NODES * 32 + 255) / 256;      // 6250 (warp per node, 256/blk)
    const int AB  = (N_NODES * 32 + 127) / 128;      // 12500 (warp per node, 128/blk)
    const int MLP1_GRID = 444;
    const int MLP_GRID  = 296;                       // 148 SMs x 2 blocks

    // CSR build (every replay; g_deg/g_stats zeroed by previous invocation)
    k_hist<<<EB4, 256>>>(dst);                 // counts + per-edge rank; zeros g_stats
    k_scan<<<1, 1024>>>();
    k_permute<<<EB4, 256>>>(src, dst);         // atomic-free scatter; zeros g_deg

    // layer 1 (scalar input) -> y, stats slot 0
    k_agg1<<<WB, 256>>>(x, eps);
    k_mlp1<<<MLP1_GRID, 128>>>(w1a, b1a, w2a, b2a);

    // layers 2-4: agg (BN of layer l folded, affine inline) + FFMA2 MLP
    for (int l = 0; l < 3; l++) {
        k_agg<<<AB, 128>>>(eps, l + 1, l, gammas + l * HID, betas + l * HID);
        k_mlp<<<MLP_GRID, 128>>>(w1s + l * HID * HID, b1s + l * HID,
                                 w2s + l * HID * HID, b2s + l * HID, l + 1);
    }

    // final FC with BN(layer 4) folded, affine inline from stats slot 3
    k_fc<<<WB, 256>>>(fcw, fcb, gammas + 3 * HID, betas + 3 * HID, out);
}